// round 10
// baseline (speedup 1.0000x reference)
#include <cuda_runtime.h>
#include <stdint.h>

// Problem constants
#define TT   384      // num_thetas (= n1 = n2)
#define NN   384      // points per space
#define RR   384      // resolution
#define D1   128
#define D2   32
#define SZ1  (D1*TT)  // 49152
#define SZ2  (D2*TT)  // 12288

// Scratch (static device globals; no allocation allowed)
__device__ float g_v1[SZ1];
__device__ float g_v2[SZ2];
__device__ float g_nh1[TT*NN];   // transposed: [t][n]
__device__ float g_nh2[TT*NN];
__device__ float g_loss;
__device__ unsigned int g_done = 0;

// ---------------------------------------------------------------------------
// Threefry2x32, key = (0, 42), partitionable layout: bits(i) = o0^o1,
// counter = (0, i)
// ---------------------------------------------------------------------------
__device__ __forceinline__ uint32_t rotl32(uint32_t x, int d) {
    return (x << d) | (x >> (32 - d));
}

__device__ __forceinline__ void threefry_0_42(uint32_t x0, uint32_t x1,
                                              uint32_t& o0, uint32_t& o1) {
    const uint32_t ks0 = 0u;
    const uint32_t ks1 = 42u;
    const uint32_t ks2 = 0u ^ 42u ^ 0x1BD11BDAu;
    x0 += ks0; x1 += ks1;
#define TF_R4(a,b,c,d)                               \
    x0 += x1; x1 = rotl32(x1,(a)); x1 ^= x0;          \
    x0 += x1; x1 = rotl32(x1,(b)); x1 ^= x0;          \
    x0 += x1; x1 = rotl32(x1,(c)); x1 ^= x0;          \
    x0 += x1; x1 = rotl32(x1,(d)); x1 ^= x0;
    TF_R4(13,15,26,6)   x0 += ks1; x1 += ks2 + 1u;
    TF_R4(17,29,16,24)  x0 += ks2; x1 += ks0 + 2u;
    TF_R4(13,15,26,6)   x0 += ks0; x1 += ks1 + 3u;
    TF_R4(17,29,16,24)  x0 += ks1; x1 += ks2 + 4u;
    TF_R4(13,15,26,6)   x0 += ks2; x1 += ks0 + 5u;
#undef TF_R4
    o0 = x0; o1 = x1;
}

// XLA ErfInv float32 polynomial (log1p -> fast MUFU log)
__device__ __forceinline__ float erfinv_fast(float x) {
    float w = -__logf(fmaf(-x, x, 1.0f));
    float p;
    if (w < 5.0f) {
        w -= 2.5f;
        p = 2.81022636e-08f;
        p = fmaf(p, w, 3.43273939e-07f);
        p = fmaf(p, w, -3.5233877e-06f);
        p = fmaf(p, w, -4.39150654e-06f);
        p = fmaf(p, w, 0.00021858087f);
        p = fmaf(p, w, -0.00125372503f);
        p = fmaf(p, w, -0.00417768164f);
        p = fmaf(p, w, 0.246640727f);
        p = fmaf(p, w, 1.50140941f);
    } else {
        w = sqrtf(w) - 3.0f;
        p = -0.000200214257f;
        p = fmaf(p, w, 0.000100950558f);
        p = fmaf(p, w, 0.00134934322f);
        p = fmaf(p, w, -0.00367342844f);
        p = fmaf(p, w, 0.00573950773f);
        p = fmaf(p, w, -0.0076224613f);
        p = fmaf(p, w, 0.00943887047f);
        p = fmaf(p, w, 1.00167406f);
        p = fmaf(p, w, 2.83297682f);
    }
    return p * x;
}

__device__ __forceinline__ float bits_to_normal(uint32_t b) {
    float f = __uint_as_float((b >> 9) | 0x3F800000u) - 1.0f;   // [0,1)
    const float lo = -0.99999994f;                               // nextafter(-1,0)
    const float span = 1.0f - lo;
    float u = fmaf(f, span, lo);
    u = fmaxf(lo, u);
    return 1.41421356f * erfinv_fast(u);   // sqrt(2)
}

// ---------------------------------------------------------------------------
// 1) Generate direction matrices: 2 independent chains per thread (ILP),
//    no reg cap so ptxas can interleave. Resets loss accumulator.
// ---------------------------------------------------------------------------
__global__ void gen_dirs_kernel() {
    int i0 = blockIdx.x * 512 + threadIdx.x;   // chains at i0 and i0+256
    int i1 = i0 + 256;
    if (i0 == 0) g_loss = 0.0f;

    uint32_t ca = (i0 < SZ1) ? (uint32_t)i0 : (uint32_t)(i0 - SZ1);
    uint32_t cb = (i1 < SZ1) ? (uint32_t)i1 : (uint32_t)(i1 - SZ1);
    uint32_t a0, a1, b0, b1;
    threefry_0_42(0u, ca, a0, a1);
    threefry_0_42(0u, cb, b0, b1);
    float va = bits_to_normal(a0 ^ a1);
    float vb = bits_to_normal(b0 ^ b1);

    if (i0 < SZ1) g_v1[i0] = va; else g_v1[0] = g_v1[0], g_v2[i0 - SZ1] = va;
    if (i1 < SZ1) g_v1[i1] = vb; else g_v2[i1 - SZ1] = vb;
}

// ---------------------------------------------------------------------------
// 2) nh^T[t][n] = (sum_k X[n,k] V[k,t]) * rsqrt(sum_k V[k,t]^2)
//    32n x 64t tile, 256 threads, 2x4 register blocking.
//    xs stored TRANSPOSED [k][n] (pad 33); vs stored [k][t] (pad 68, float4).
//    blockIdx.z: 0 -> space1 (D=128), 1 -> space2 (D=32)
// ---------------------------------------------------------------------------
__global__ void __launch_bounds__(256)
gemm_kernel(const float* __restrict__ s1, const float* __restrict__ s2) {
    int space = blockIdx.z;
    const float* X = space ? s2 : s1;
    const float* V = space ? g_v2 : g_v1;
    float* OUT     = space ? g_nh2 : g_nh1;
    const int D    = space ? D2 : D1;
    const int KT   = D / 32;

    int n0 = blockIdx.x * 32;
    int t0 = blockIdx.y * 64;
    int tx = threadIdx.x;           // 0..15 -> n, n+16
    int ty = threadIdx.y;           // 0..15 -> t*4 .. t*4+3
    int lin = ty * 16 + tx;

    __shared__ float xs[32][33];        // [k][n] transposed
    __shared__ float vs[32][68];        // [k][t], 68 floats/row (16B-aligned rows)
    __shared__ float nrm[64];
    __shared__ float inv[64];

    if (lin < 64) nrm[lin] = 0.0f;
    __syncthreads();

    // loader mappings
    int xk = lin & 31, xg = lin >> 5;   // X: 4 elems (rows n = j*8+xg)
    int vt = lin & 63, vg = lin >> 6;   // V: 8 elems (rows k = j*4+vg)

    float nsum = 0.0f;                  // norm partial for column (t0+vt)
    float acc[8];
    #pragma unroll
    for (int i = 0; i < 8; i++) acc[i] = 0.0f;

    for (int u = 0; u < KT; u++) {
        int k0 = u * 32;
        #pragma unroll
        for (int j = 0; j < 4; j++) {
            int n = j * 8 + xg;
            xs[xk][n] = X[(n0 + n) * D + (k0 + xk)];   // coalesced over xk
        }
        #pragma unroll
        for (int j = 0; j < 8; j++) {
            int k = j * 4 + vg;
            float v = V[(k0 + k) * TT + (t0 + vt)];    // coalesced over vt
            vs[k][vt] = v;
            nsum = fmaf(v, v, nsum);
        }
        __syncthreads();
        #pragma unroll
        for (int k = 0; k < 32; k++) {
            float4 vv = *(const float4*)&vs[k][ty * 4];
            float x0 = xs[k][tx];
            float x1 = xs[k][tx + 16];
            acc[0] = fmaf(x0, vv.x, acc[0]);
            acc[1] = fmaf(x0, vv.y, acc[1]);
            acc[2] = fmaf(x0, vv.z, acc[2]);
            acc[3] = fmaf(x0, vv.w, acc[3]);
            acc[4] = fmaf(x1, vv.x, acc[4]);
            acc[5] = fmaf(x1, vv.y, acc[5]);
            acc[6] = fmaf(x1, vv.z, acc[6]);
            acc[7] = fmaf(x1, vv.w, acc[7]);
        }
        __syncthreads();
    }
    atomicAdd(&nrm[vt], nsum);          // 4 partials per column
    __syncthreads();
    if (lin < 64) inv[lin] = rsqrtf(nrm[lin]);
    __syncthreads();

    #pragma unroll
    for (int i = 0; i < 4; i++) {
        int t = t0 + ty * 4 + i;
        float iv = inv[ty * 4 + i];
        OUT[t * NN + (n0 + tx)]      = acc[i]     * iv;
        OUT[t * NN + (n0 + tx + 16)] = acc[i + 4] * iv;
    }
}

// ---------------------------------------------------------------------------
// 3) ECT difference + loss via counting-sort CSR + GATHER (no float atomics).
// ---------------------------------------------------------------------------
__device__ __forceinline__ float tanh_hw(float x) {
    float y;
    asm("tanh.approx.f32 %0, %1;" : "=f"(y) : "f"(x));
    return y;
}

#define ECT_THREADS 416   // 13 warps: covers 392-bucket scan
#define NB 392

__global__ void __launch_bounds__(ECT_THREADS)
ect_loss_kernel(float* __restrict__ out) {
    int t    = blockIdx.x;
    int tid  = threadIdx.x;               // 0..415
    int lane = tid & 31, wid = tid >> 5;  // 13 warps

    __shared__ unsigned pcnt[NB];         // packed bucket counts
    __shared__ unsigned est[NB + 1];      // packed exclusive starts
    __shared__ float    sval1[NN];        // CSR: b = -250*(1+nh), space1
    __shared__ float    sval2[NN];        // CSR space2
    __shared__ unsigned wsum[13];
    __shared__ unsigned wofs[13];
    __shared__ float    ps[13];

    if (tid < NB) pcnt[tid] = 0u;
    __syncthreads();

    const float AI   = 383.0f / 2.0f;     // 1/H
    const float H250 = 500.0f / 383.0f;   // (z/2) step per bin

    // Phase 1: count (packed atomic; return value = rank within bucket)
    int B1 = 0, B2 = 0;
    unsigned rk1 = 0, rk2 = 0;
    float b1 = 0.0f, b2 = 0.0f;
    if (tid < NN) {
        float nh1 = g_nh1[t * NN + tid];
        float nh2 = g_nh2[t * NN + tid];
        int ia1 = (int)floorf((nh1 + 1.0f) * AI);
        int ia2 = (int)floorf((nh2 + 1.0f) * AI);
        B1 = (ia1 <= -4) ? 0 : ((ia1 >= 387) ? 391 : ia1 + 4);
        B2 = (ia2 <= -4) ? 0 : ((ia2 >= 387) ? 391 : ia2 + 4);
        b1 = -250.0f * (1.0f + nh1);
        b2 = -250.0f * (1.0f + nh2);
        rk1 = atomicAdd(&pcnt[B1], 0x10000u) >> 16;
        rk2 = atomicAdd(&pcnt[B2], 1u) & 0xFFFFu;
    }
    __syncthreads();

    // Phase 2: exclusive scan of packed counts (no cross-field carry)
    unsigned v = (tid < NB) ? pcnt[tid] : 0u;
    unsigned iv = v;
    #pragma unroll
    for (int o = 1; o < 32; o <<= 1) {
        unsigned y = __shfl_up_sync(0xffffffffu, iv, o);
        if (lane >= o) iv += y;
    }
    if (lane == 31) wsum[wid] = iv;
    __syncthreads();
    if (tid < 32) {
        unsigned a = (tid < 13) ? wsum[tid] : 0u;
        #pragma unroll
        for (int o = 1; o < 32; o <<= 1) {
            unsigned y = __shfl_up_sync(0xffffffffu, a, o);
            if (tid >= o) a += y;
        }
        if (tid < 13) wofs[tid] = a;
    }
    __syncthreads();
    unsigned incl = iv + (wid ? wofs[wid - 1] : 0u);
    if (tid < NB) est[tid] = incl - v;
    if (tid == NB - 1) est[NB] = incl;
    __syncthreads();

    // Phase 3: scatter (conflict-free; slots unique)
    if (tid < NN) {
        sval1[(est[B1] >> 16) + rk1]     = b1;
        sval2[(est[B2] & 0xFFFFu) + rk2] = b2;
    }
    __syncthreads();

    // Phase 4: gather per bin r = tid (tid < 384)
    float sq = 0.0f;
    if (tid < RR) {
        unsigned eL = est[tid + 1];
        unsigned eR = est[tid + 8];
        float acc = (float)((int)(eL >> 16) - (int)(eL & 0xFFFFu));
        float rz  = (float)tid * H250;
        int j0 = (int)(eL >> 16),     j1 = (int)(eR >> 16);
        int k0 = (int)(eL & 0xFFFFu), k1 = (int)(eR & 0xFFFFu);
        for (int j = j0; j < j1; j++)
            acc += fmaf(0.5f, tanh_hw(rz + sval1[j]), 0.5f);
        for (int k = k0; k < k1; k++)
            acc -= fmaf(0.5f, tanh_hw(rz + sval2[k]), 0.5f);
        sq = acc * acc;
    }

    // block reduce
    #pragma unroll
    for (int o = 16; o; o >>= 1) sq += __shfl_down_sync(0xffffffffu, sq, o);
    if (lane == 0) ps[wid] = sq;
    __syncthreads();
    if (tid == 0) {
        float s = 0.0f;
        #pragma unroll
        for (int i = 0; i < 13; i++) s += ps[i];
        atomicAdd(&g_loss, s);
        __threadfence();
        unsigned prev = atomicAdd(&g_done, 1u);
        if (prev == (unsigned)(gridDim.x - 1)) {
            g_done = 0u;  // self-reset for graph replay
            float total = *((volatile float*)&g_loss);
            out[0] = total * (1.0f / (float)(RR * TT));
        }
    }
}

extern "C" void kernel_launch(void* const* d_in, const int* in_sizes, int n_in,
                              void* d_out, int out_size) {
    const float* s1 = (const float*)d_in[0];   // [384, 128]
    const float* s2 = (const float*)d_in[1];   // [384, 32]
    float* out = (float*)d_out;

    gen_dirs_kernel<<<120, 256>>>();           // 2 elements/thread = 61440
    gemm_kernel<<<dim3(NN / 32, TT / 64, 2), dim3(16, 16)>>>(s1, s2);
    ect_loss_kernel<<<TT, ECT_THREADS>>>(out);
}